// round 15
// baseline (speedup 1.0000x reference)
#include <cuda_runtime.h>
#include <cuda_bf16.h>
#include <cuda_fp16.h>

// ---------------- problem constants ----------------
#define BATCH   64
#define T_IN    8192
#define T2      4096        // after pool1
#define T4      2048        // after pool2
#define N_NODES 131072      // BATCH * T4
#define N_EDGES 2097152
#define HID     64
#define OUTC    10

typedef unsigned long long u64;

// m16n8k16 fp16 MMA, fp32 accumulate (HMMA)
__device__ __forceinline__ void mma16816(float* d, const unsigned* a, const unsigned* b) {
    asm volatile(
        "mma.sync.aligned.m16n8k16.row.col.f32.f16.f16.f32 "
        "{%0,%1,%2,%3}, {%4,%5,%6,%7}, {%8,%9}, {%0,%1,%2,%3};"
        : "+f"(d[0]), "+f"(d[1]), "+f"(d[2]), "+f"(d[3])
        : "r"(a[0]), "r"(a[1]), "r"(a[2]), "r"(a[3]), "r"(b[0]), "r"(b[1]));
}

__device__ __forceinline__ unsigned h2u(__half2 h) { return *(unsigned*)&h; }

// ---------------- scratch (device globals, no allocation) ----------------
// NOTE: referenced ONLY inside device code (GB300 ATS silently reads the host
// shadow if passed as host-side kernel args).
__device__ __half2 g_feat_h[N_NODES * 16];       // conv2 out * dis, fp16, node-major
__device__ float   g_z[N_NODES * 32];            // aggregated 32-dim features (fp32)
__device__ __half2 g_y_h[N_NODES * 32];          // dis * (relu(z@W1+b1) @ W2), fp16
__device__ float   g_pool[BATCH * 64];           // per-batch channel sums
__device__ float   g_dis[N_NODES];
__device__ int     g_cnt[N_NODES];
__device__ int     g_off[N_NODES + 1];
__device__ int     g_cur[N_NODES];
__device__ int     g_srcs[N_EDGES];
__device__ int     g_bsum[128];

// ---------------- conv via tensor cores: 2x im2col GEMM ---------------------
// Block = 256 threads, 128 output nodes. K padded to 128 (16 ci x 8, kk 5..7
// zero) so k-chunks never straddle channels. Weights hi/lo split (fp16 pair)
// to cancel common-mode weight quantization.
//
// Shared layout (halves, dynamic):
//  sxh [16][544]  x tile fp16 (valid 527)             0     .. 8704
//  sc1 [528][18]  raw conv1 outputs fp16              8704  .. 18208
//  sh1 [16][264]  pooled conv1 (ci-major, 260+4 zero) 18208 .. 22432
//  w1h/w1l [16][128], w2h/w2l [32][128]               22432 .. 34720
//  b1f[16], b2f[32] floats at byte 69440; total 69632 B (3 blocks/SM)
//  sC2 [256][34] raw conv2 fp16 ALIASES sxh (dead after phase-1 MMAs)
#define CVX_STR  544
#define CVC1_STR 18
#define CVH1_STR 264
#define CVC2_STR 34
#define CV_SM_BYTES 69632

__global__ void __launch_bounds__(256)
conv_mma_kernel(const float* __restrict__ x,
                const float* __restrict__ w1,
                const float* __restrict__ b1,
                const float* __restrict__ w2,
                const float* __restrict__ b2) {
    extern __shared__ __half smh[];
    __half* sxh = smh;                      // [16][544]
    __half* sc1 = smh + 8704;               // [528][18]
    __half* sh1 = smh + 18208;              // [16][264]
    __half* w1h = smh + 22432;              // [16][128]
    __half* w1l = w1h + 2048;
    __half* w2h = w1l + 2048;               // [32][128]
    __half* w2l = w2h + 4096;
    float*  b1f = (float*)(smh + 34720);    // [16]
    float*  b2f = b1f + 16;                 // [32]
    __half* sC2 = smh;                      // [256][34] alias sxh

    const int tile = blockIdx.x, bb = blockIdx.y, tid = threadIdx.x;
    const int w = tid >> 5, lane = tid & 31, g = lane >> 2, t = lane & 3;

    // ---- loads ----
    const int x0 = tile * 512 - 6;   // 527 valid elements (0..526), rest zero
    for (int i = tid; i < 16 * 272; i += 256) {
        int ci = i / 272, jh = i - ci * 272;
        int i0 = 2 * jh;
        const float* xr = x + (size_t)(bb * 16 + ci) * T_IN;
        int e0 = x0 + i0, e1 = e0 + 1;
        float a = (i0 < 527 && e0 >= 0 && e0 < T_IN) ? xr[e0] : 0.f;
        float b = (i0 + 1 < 527 && e1 >= 0 && e1 < T_IN) ? xr[e1] : 0.f;
        *(__half2*)&sxh[ci * CVX_STR + i0] = __floats2half2_rn(a, b);
    }
    for (int i = tid; i < 16 * 128; i += 256) {          // W1 [co][ci*8+kk]
        int co = i >> 7, c = i & 127, ci = c >> 3, kk = c & 7;
        float v = (kk < 5) ? w1[(co * 16 + ci) * 5 + kk] : 0.f;
        __half hi = __float2half_rn(v);
        w1h[i] = hi;
        w1l[i] = __float2half_rn(v - __half2float(hi));
    }
    for (int i = tid; i < 32 * 128; i += 256) {          // W2 [co][ci*8+kk]
        int co = i >> 7, c = i & 127, ci = c >> 3, kk = c & 7;
        float v = (kk < 5) ? w2[(co * 16 + ci) * 5 + kk] : 0.f;
        __half hi = __float2half_rn(v);
        w2h[i] = hi;
        w2l[i] = __float2half_rn(v - __half2float(hi));
    }
    if (tid < 16) b1f[tid] = b1[tid];
    else if (tid < 48) b2f[tid - 16] = b2[tid - 16];
    __syncthreads();

    // ---- phase 1 MMA: conv1 raw [520 pos x 16 co] -> sc1 ----
    for (int mt = w; mt < 33; mt += 8) {
        const int m0 = mt * 16;
        float acc[2][4];
#pragma unroll
        for (int nf = 0; nf < 2; nf++)
#pragma unroll
            for (int q = 0; q < 4; q++) acc[nf][q] = 0.f;
#pragma unroll
        for (int kc = 0; kc < 8; kc++) {
            const __half* xa = &sxh[(2 * kc) * CVX_STR + m0 + g + 2 * t];
            const __half* xb = &sxh[(2 * kc + 1) * CVX_STR + m0 + g + 2 * t];
            unsigned a[4];
            a[0] = h2u(__halves2half2(xa[0], xa[1]));
            a[1] = h2u(__halves2half2(xa[8], xa[9]));
            a[2] = h2u(__halves2half2(xb[0], xb[1]));
            a[3] = h2u(__halves2half2(xb[8], xb[9]));
#pragma unroll
            for (int nf = 0; nf < 2; nf++) {
                const __half* Bh = &w1h[(nf * 8 + g) * 128 + kc * 16 + 2 * t];
                const __half* Bl = &w1l[(nf * 8 + g) * 128 + kc * 16 + 2 * t];
                unsigned bv[2];
                bv[0] = *(const unsigned*)&Bh[0]; bv[1] = *(const unsigned*)&Bh[8];
                mma16816(acc[nf], a, bv);
                bv[0] = *(const unsigned*)&Bl[0]; bv[1] = *(const unsigned*)&Bl[8];
                mma16816(acc[nf], a, bv);
            }
        }
#pragma unroll
        for (int nf = 0; nf < 2; nf++) {
            *(__half2*)&sc1[(m0 + g) * CVC1_STR + nf * 8 + 2 * t] =
                __floats2half2_rn(acc[nf][0], acc[nf][1]);
            *(__half2*)&sc1[(m0 + g + 8) * CVC1_STR + nf * 8 + 2 * t] =
                __floats2half2_rn(acc[nf][2], acc[nf][3]);
        }
    }
    __syncthreads();

    // ---- pool + bias + relu -> sh1 (ci-major), zero tail ----
    const int q0 = tile * 256 - 2;
    for (int i = tid; i < 16 * 264; i += 256) {
        int j = i >> 4, co = i & 15;
        float v = 0.f;
        if (j < 260) {
            int q = q0 + j;
            if (q >= 0 && q < T2) {
                float c0 = __half2float(sc1[(2 * j) * CVC1_STR + co]);
                float c1 = __half2float(sc1[(2 * j + 1) * CVC1_STR + co]);
                v = fmaxf(fmaxf(c0, c1) + b1f[co], 0.f);
            }
        }
        sh1[co * CVH1_STR + j] = __float2half_rn(v);
    }
    __syncthreads();

    // ---- phase 2 MMA: conv2 raw [256 pos x 32 co] -> sC2 (alias sxh) ----
#pragma unroll
    for (int mi = 0; mi < 2; mi++) {
        const int m0 = (2 * w + mi) * 16;
        float acc[4][4];
#pragma unroll
        for (int nf = 0; nf < 4; nf++)
#pragma unroll
            for (int q = 0; q < 4; q++) acc[nf][q] = 0.f;
#pragma unroll
        for (int kc = 0; kc < 8; kc++) {
            const __half* ha = &sh1[(2 * kc) * CVH1_STR + m0 + g + 2 * t];
            const __half* hb = &sh1[(2 * kc + 1) * CVH1_STR + m0 + g + 2 * t];
            unsigned a[4];
            a[0] = h2u(__halves2half2(ha[0], ha[1]));
            a[1] = h2u(__halves2half2(ha[8], ha[9]));
            a[2] = h2u(__halves2half2(hb[0], hb[1]));
            a[3] = h2u(__halves2half2(hb[8], hb[9]));
#pragma unroll
            for (int nf = 0; nf < 4; nf++) {
                const __half* Bh = &w2h[(nf * 8 + g) * 128 + kc * 16 + 2 * t];
                const __half* Bl = &w2l[(nf * 8 + g) * 128 + kc * 16 + 2 * t];
                unsigned bv[2];
                bv[0] = *(const unsigned*)&Bh[0]; bv[1] = *(const unsigned*)&Bh[8];
                mma16816(acc[nf], a, bv);
                bv[0] = *(const unsigned*)&Bl[0]; bv[1] = *(const unsigned*)&Bl[8];
                mma16816(acc[nf], a, bv);
            }
        }
#pragma unroll
        for (int nf = 0; nf < 4; nf++) {
            *(__half2*)&sC2[(m0 + g) * CVC2_STR + nf * 8 + 2 * t] =
                __floats2half2_rn(acc[nf][0], acc[nf][1]);
            *(__half2*)&sC2[(m0 + g + 8) * CVC2_STR + nf * 8 + 2 * t] =
                __floats2half2_rn(acc[nf][2], acc[nf][3]);
        }
    }
    __syncthreads();

    // ---- pool + bias + relu + dis, fp16 node-major write ----
    const int node_base = bb * T4 + tile * 128;
    for (int i = tid; i < 128 * 16; i += 256) {
        int lp = i >> 4, c = i & 15;
        float2 u = __half22float2(*(__half2*)&sC2[(2 * lp) * CVC2_STR + 2 * c]);
        float2 v = __half22float2(*(__half2*)&sC2[(2 * lp + 1) * CVC2_STR + 2 * c]);
        const float d = __ldg(&g_dis[node_base + lp]);
        float r0 = fmaxf(fmaxf(u.x, v.x) + b2f[2 * c], 0.f) * d;
        float r1 = fmaxf(fmaxf(u.y, v.y) + b2f[2 * c + 1], 0.f) * d;
        g_feat_h[(node_base + lp) * 16 + c] = __floats2half2_rn(r0, r1);
    }
}

// ---------------- CSR build ----------------
__global__ void zero_cnt_kernel() {
    int i = blockIdx.x * blockDim.x + threadIdx.x;
    if (i < N_NODES) g_cnt[i] = 0;
    if (i < BATCH * 64) g_pool[i] = 0.f;
}

__global__ void hist_kernel(const int* __restrict__ col) {
    int e = blockIdx.x * blockDim.x + threadIdx.x;
    if (e < N_EDGES) atomicAdd(&g_cnt[col[e]], 1);
}

__global__ void scan1_kernel() {
    __shared__ int ss[256];
    const int tid = threadIdx.x;
    const int base = blockIdx.x * 1024 + tid * 4;
    int v0 = g_cnt[base], v1 = g_cnt[base + 1], v2 = g_cnt[base + 2], v3 = g_cnt[base + 3];
    g_dis[base]     = rsqrtf((float)(v0 + 1));
    g_dis[base + 1] = rsqrtf((float)(v1 + 1));
    g_dis[base + 2] = rsqrtf((float)(v2 + 1));
    g_dis[base + 3] = rsqrtf((float)(v3 + 1));
    int tsum = v0 + v1 + v2 + v3;
    ss[tid] = tsum;
    __syncthreads();
    for (int d = 1; d < 256; d <<= 1) {
        int t = (tid >= d) ? ss[tid - d] : 0;
        __syncthreads();
        ss[tid] += t;
        __syncthreads();
    }
    int excl = ss[tid] - tsum;
    g_off[base]     = excl;
    g_off[base + 1] = excl + v0;
    g_off[base + 2] = excl + v0 + v1;
    g_off[base + 3] = excl + v0 + v1 + v2;
    if (tid == 255) g_bsum[blockIdx.x] = ss[255];
}

__global__ void scan2_kernel() {
    __shared__ int ss[128];
    const int tid = threadIdx.x;
    int v = g_bsum[tid];
    ss[tid] = v;
    __syncthreads();
    for (int d = 1; d < 128; d <<= 1) {
        int t = (tid >= d) ? ss[tid - d] : 0;
        __syncthreads();
        ss[tid] += t;
        __syncthreads();
    }
    g_bsum[tid] = ss[tid] - v;
}

__global__ void scan3_kernel() {
    int i = blockIdx.x * blockDim.x + threadIdx.x;
    if (i < N_NODES) {
        int o = g_off[i] + g_bsum[i >> 10];
        g_off[i] = o;
        g_cur[i] = o;
        if (i == 0) g_off[N_NODES] = N_EDGES;
    }
}

__global__ void place_kernel(const int* __restrict__ row, const int* __restrict__ col) {
    int e = blockIdx.x * blockDim.x + threadIdx.x;
    if (e < N_EDGES) {
        int c = col[e];
        int p = atomicAdd(&g_cur[c], 1);
        g_srcs[p] = row[e];
    }
}

// ---------------- gather32 (fp16): z[i] = dis_i * (feat~[i] + sum feat~[j]) ----
__global__ void gather32_kernel() {
    const int gw = (blockIdx.x * 256 + threadIdx.x) >> 5;
    const int lane = threadIdx.x & 31;
    const int hw = lane >> 4, c = lane & 15;
    const __half2* __restrict__ y = g_feat_h;

    float ax = 0.f, ay = 0.f;
    int p = g_off[gw];
    const int e = g_off[gw + 1];
    for (; p + 8 <= e; p += 8) {
        int j0 = __ldg(&g_srcs[p + 0 + hw]);
        int j1 = __ldg(&g_srcs[p + 2 + hw]);
        int j2 = __ldg(&g_srcs[p + 4 + hw]);
        int j3 = __ldg(&g_srcs[p + 6 + hw]);
        float2 v0 = __half22float2(__ldg(&y[j0 * 16 + c]));
        float2 v1 = __half22float2(__ldg(&y[j1 * 16 + c]));
        float2 v2 = __half22float2(__ldg(&y[j2 * 16 + c]));
        float2 v3 = __half22float2(__ldg(&y[j3 * 16 + c]));
        ax += (v0.x + v1.x) + (v2.x + v3.x);
        ay += (v0.y + v1.y) + (v2.y + v3.y);
    }
    for (; p + 2 <= e; p += 2) {
        int j = __ldg(&g_srcs[p + hw]);
        float2 v = __half22float2(__ldg(&y[j * 16 + c]));
        ax += v.x; ay += v.y;
    }
    if (p < e && hw == 0) {
        int j = __ldg(&g_srcs[p]);
        float2 v = __half22float2(__ldg(&y[j * 16 + c]));
        ax += v.x; ay += v.y;
    }
    ax += __shfl_xor_sync(0xFFFFFFFFu, ax, 16);
    ay += __shfl_xor_sync(0xFFFFFFFFu, ay, 16);
    if (lane < 16) {
        float2 self = __half22float2(__ldg(&y[gw * 16 + c]));
        const float d = g_dis[gw];
        float2 r;
        r.x = (self.x + ax) * d;
        r.y = (self.y + ay) * d;
        ((float2*)g_z)[gw * 16 + c] = r;
    }
}

// ---------------- xw via tensor cores (HMMA, hi/lo weight split) -------------
__global__ void __launch_bounds__(256)
xw_mma_kernel(const float* __restrict__ W1,
              const float* __restrict__ b1,
              const float* __restrict__ W2) {
    __shared__ __align__(16) __half sW1h[64 * 40];   // [n][k], stride 40
    __shared__ __align__(16) __half sW1l[64 * 40];
    __shared__ __align__(16) __half sW2h[64 * 72];   // [n][k], stride 72
    __shared__ __align__(16) __half sW2l[64 * 72];
    __shared__ float sb1v[64];
    __shared__ __align__(16) __half sH[8][16 * 72];  // per-warp h, row stride 72

    const int tid = threadIdx.x;
    for (int i = tid; i < 32 * 64; i += 256) {
        int k = i >> 6, n = i & 63;
        float v = W1[i];
        __half hi = __float2half_rn(v);
        sW1h[n * 40 + k] = hi;
        sW1l[n * 40 + k] = __float2half_rn(v - __half2float(hi));
    }
    for (int i = tid; i < 64 * 64; i += 256) {
        int k = i >> 6, n = i & 63;
        float v = W2[i];
        __half hi = __float2half_rn(v);
        sW2h[n * 72 + k] = hi;
        sW2l[n * 72 + k] = __float2half_rn(v - __half2float(hi));
    }
    if (tid < 64) sb1v[tid] = b1[tid];
    __syncthreads();

    const int w = tid >> 5, lane = tid & 31;
    const int g = lane >> 2, t = lane & 3;
    const int nb = blockIdx.x * 128 + w * 16;
    __half* H = &sH[w][0];

    // ---- stage 1: C1[16x64] = A(z)[16x32] @ W1[32x64] ----
    float acc[8][4];
#pragma unroll
    for (int nf = 0; nf < 8; nf++)
#pragma unroll
        for (int q = 0; q < 4; q++) acc[nf][q] = 0.f;

#pragma unroll
    for (int kf = 0; kf < 2; kf++) {
        const int k0 = kf * 16;
        unsigned a[4];
        {
            float2 v;
            v = *(const float2*)&g_z[(size_t)(nb + g) * 32 + k0 + 2 * t];
            __half2 h = __floats2half2_rn(v.x, v.y); a[0] = h2u(h);
            v = *(const float2*)&g_z[(size_t)(nb + g + 8) * 32 + k0 + 2 * t];
            h = __floats2half2_rn(v.x, v.y); a[1] = h2u(h);
            v = *(const float2*)&g_z[(size_t)(nb + g) * 32 + k0 + 2 * t + 8];
            h = __floats2half2_rn(v.x, v.y); a[2] = h2u(h);
            v = *(const float2*)&g_z[(size_t)(nb + g + 8) * 32 + k0 + 2 * t + 8];
            h = __floats2half2_rn(v.x, v.y); a[3] = h2u(h);
        }
#pragma unroll
        for (int nf = 0; nf < 8; nf++) {
            unsigned bv[2];
            bv[0] = *(const unsigned*)&sW1h[(nf * 8 + g) * 40 + k0 + 2 * t];
            bv[1] = *(const unsigned*)&sW1h[(nf * 8 + g) * 40 + k0 + 2 * t + 8];
            mma16816(acc[nf], a, bv);
            bv[0] = *(const unsigned*)&sW1l[(nf * 8 + g) * 40 + k0 + 2 * t];
            bv[1] = *(const unsigned*)&sW1l[(nf * 8 + g) * 40 + k0 + 2 * t + 8];
            mma16816(acc[nf], a, bv);
        }
    }

    // ---- bias + relu -> fp16 staging ----
#pragma unroll
    for (int nf = 0; nf < 8; nf++) {
        const int c0 = nf * 8 + 2 * t;
        float h0 = fmaxf(acc[nf][0] + sb1v[c0],     0.f);
        float h1 = fmaxf(acc[nf][1] + sb1v[c0 + 1], 0.f);
        float h2 = fmaxf(acc[nf][2] + sb1v[c0],     0.f);
        float h3 = fmaxf(acc[nf][3] + sb1v[c0 + 1], 0.f);
        *(__half2*)&H[g * 72 + c0]       = __floats2half2_rn(h0, h1);
        *(__half2*)&H[(g + 8) * 72 + c0] = __floats2half2_rn(h2, h3);
    }
    __syncwarp();

    // ---- stage 2: C2[16x64] = h[16x64] @ W2[64x64] ----
    float acc2[8][4];
#pragma unroll
    for (int nf = 0; nf < 8; nf++)
#pragma unroll
        for (int q = 0; q < 4; q++) acc2[nf][q] = 0.f;

#pragma unroll
    for (int kf = 0; kf < 4; kf++) {
        const int k0 = kf * 16;
        unsigned a[4];
        a[0] = *(const unsigned*)&H[g * 72 + k0 + 2 * t];
        a[1] = *(const unsigned*)&H[(g + 8) * 72 + k0 + 2 * t];
        a[2] = *(const unsigned*)&H[g * 72 + k0 + 2 * t + 8];
        a[3] = *(const unsigned*)&H[(g + 8) * 72 + k0 + 2 * t + 8];
#pragma unroll
        for (int nf = 0; nf < 8; nf++) {
            unsigned bv[2];
            bv[0] = *(const unsigned*)&sW2h[(nf * 8 + g) * 72 + k0 + 2 * t];
            bv[1] = *(const unsigned*)&sW2h[(nf * 8 + g) * 72 + k0 + 2 * t + 8];
            mma16816(acc2[nf], a, bv);
            bv[0] = *(const unsigned*)&sW2l[(nf * 8 + g) * 72 + k0 + 2 * t];
            bv[1] = *(const unsigned*)&sW2l[(nf * 8 + g) * 72 + k0 + 2 * t + 8];
            mma16816(acc2[nf], a, bv);
        }
    }

    // ---- dis scale + fp16 write ----
    const float d0 = g_dis[nb + g], d1 = g_dis[nb + g + 8];
    __half2* y0 = g_y_h + (size_t)(nb + g) * 32;
    __half2* y1 = g_y_h + (size_t)(nb + g + 8) * 32;
#pragma unroll
    for (int nf = 0; nf < 8; nf++) {
        const int cw = nf * 4 + t;
        y0[cw] = __floats2half2_rn(acc2[nf][0] * d0, acc2[nf][1] * d0);
        y1[cw] = __floats2half2_rn(acc2[nf][2] * d1, acc2[nf][3] * d1);
    }
}

// ---------------- gather64 + fused mean-pool partial reduction ----------------
__global__ void gather64_pool_kernel(const float* __restrict__ bias) {
    __shared__ float pool[64];
    const __half2* __restrict__ y = g_y_h;
    const int tid = threadIdx.x;
    const int gw = (blockIdx.x * 256 + tid) >> 5;
    const int lane = tid & 31;
    if (tid < 64) pool[tid] = 0.f;
    __syncthreads();

    float2 a = __half22float2(__ldg(&y[gw * 32 + lane]));
    int p = g_off[gw];
    const int e = g_off[gw + 1];
    for (; p + 8 <= e; p += 8) {
        int j0 = __ldg(&g_srcs[p + 0]), j1 = __ldg(&g_srcs[p + 1]);
        int j2 = __ldg(&g_srcs[p + 2]), j3 = __ldg(&g_srcs[p + 3]);
        int j4 = __ldg(&g_srcs[p + 4]), j5 = __ldg(&g_srcs[p + 5]);
        int j6 = __ldg(&g_srcs[p + 6]), j7 = __ldg(&g_srcs[p + 7]);
        float2 v0 = __half22float2(__ldg(&y[j0 * 32 + lane]));
        float2 v1 = __half22float2(__ldg(&y[j1 * 32 + lane]));
        float2 v2 = __half22float2(__ldg(&y[j2 * 32 + lane]));
        float2 v3 = __half22float2(__ldg(&y[j3 * 32 + lane]));
        float2 v4 = __half22float2(__ldg(&y[j4 * 32 + lane]));
        float2 v5 = __half22float2(__ldg(&y[j5 * 32 + lane]));
        float2 v6 = __half22float2(__ldg(&y[j6 * 32 + lane]));
        float2 v7 = __half22float2(__ldg(&y[j7 * 32 + lane]));
        a.x += ((v0.x + v1.x) + (v2.x + v3.x)) + ((v4.x + v5.x) + (v6.x + v7.x));
        a.y += ((v0.y + v1.y) + (v2.y + v3.y)) + ((v4.y + v5.y) + (v6.y + v7.y));
    }
    for (; p < e; p++) {
        int j = __ldg(&g_srcs[p]);
        float2 v = __half22float2(__ldg(&y[j * 32 + lane]));
        a.x += v.x; a.y += v.y;
    }
    const float d = g_dis[gw];
    float2 bb = ((const float2*)bias)[lane];
    float rx = fmaxf(fmaf(d, a.x, bb.x), 0.f);
    float ry = fmaxf(fmaf(d, a.y, bb.y), 0.f);
    atomicAdd(&pool[2 * lane],     rx);
    atomicAdd(&pool[2 * lane + 1], ry);
    __syncthreads();
    if (tid < 64) {
        const int batch = gw >> 11;
        atomicAdd(&g_pool[batch * 64 + tid], pool[tid]);
    }
}

// ---------------- classifier from pooled sums ----------------
__global__ void cls_kernel(const float* __restrict__ clsw,
                           const float* __restrict__ clsb,
                           float* __restrict__ out) {
    __shared__ float sw[64 * OUTC];
    const int tid = threadIdx.x;
    if (tid < 64 * OUTC) sw[tid] = clsw[tid];
    __syncthreads();
    if (tid < BATCH * OUTC) {
        const int b = tid / OUTC, o = tid - b * OUTC;
        float acc = clsb[o];
#pragma unroll
        for (int c = 0; c < 64; c++)
            acc += g_pool[b * 64 + c] * sw[c * OUTC + o];
        out[tid] = acc * (1.f / (float)T4) + clsb[o] * (1.f - 1.f / (float)T4);
    }
}

// ---------------- launch ----------------
extern "C" void kernel_launch(void* const* d_in, const int* in_sizes, int n_in,
                              void* d_out, int out_size) {
    const float* x       = nullptr;
    const int*   ei      = nullptr;
    const float* conv1_w = nullptr; const float* conv1_b = nullptr;
    const float* conv2_w = nullptr; const float* conv2_b = nullptr;
    const float* gcn1_w  = nullptr; const float* gcn1_b  = nullptr;
    const float* gcn2_w  = nullptr; const float* gcn2_b  = nullptr;
    const float* cls_w   = nullptr; const float* cls_b   = nullptr;

    for (int i = 0; i < n_in; i++) {
        switch (in_sizes[i]) {
            case BATCH * 16 * T_IN:   x       = (const float*)d_in[i]; break;
            case 2 * N_EDGES:         ei      = (const int*)  d_in[i]; break;
            case 16 * 16 * 5:         conv1_w = (const float*)d_in[i]; break;
            case 16:                  conv1_b = (const float*)d_in[i]; break;
            case 32 * 16 * 5:         conv2_w = (const float*)d_in[i]; break;
            case 32:                  conv2_b = (const float*)d_in[i]; break;
            case 32 * HID:            gcn1_w  = (const float*)d_in[i]; break;
            case HID * HID:           gcn2_w  = (const float*)d_in[i]; break;
            case HID * OUTC:          cls_w   = (const float*)d_in[i]; break;
            case OUTC:                cls_b   = (const float*)d_in[i]; break;
            case HID:
                if (!gcn1_b) gcn1_b = (const float*)d_in[i];
                else         gcn2_b = (const float*)d_in[i];
                break;
            default: break;
        }
    }
    if (!x || !ei || !conv1_w || !conv2_w || !gcn1_w || !gcn2_w || !cls_w) {
        x       = (const float*)d_in[0];  ei      = (const int*)  d_in[1];
        conv1_w = (const float*)d_in[2];  conv1_b = (const float*)d_in[3];
        conv2_w = (const float*)d_in[4];  conv2_b = (const float*)d_in[5];
        gcn1_w  = (const float*)d_in[6];  gcn1_b  = (const float*)d_in[7];
        gcn2_w  = (const float*)d_in[8];  gcn2_b  = (const float*)d_in[9];
        cls_w   = (const float*)d_in[10]; cls_b   = (const float*)d_in[11];
    }

    float* out = (float*)d_out;
    const int* e_row = ei;
    const int* e_col = ei + N_EDGES;

    cudaFuncSetAttribute(conv_mma_kernel,
                         cudaFuncAttributeMaxDynamicSharedMemorySize, CV_SM_BYTES);

    static cudaStream_t s_side = nullptr;
    static cudaEvent_t  s_fork = nullptr, s_join = nullptr;
    if (!s_side) {
        cudaStreamCreateWithFlags(&s_side, cudaStreamNonBlocking);
        cudaEventCreateWithFlags(&s_fork, cudaEventDisableTiming);
        cudaEventCreateWithFlags(&s_join, cudaEventDisableTiming);
    }

    // shared prefix: counts + dis (conv needs dis; CSR tail needs counts)
    zero_cnt_kernel<<<N_NODES / 256, 256>>>();
    hist_kernel<<<N_EDGES / 256, 256>>>(e_col);
    scan1_kernel<<<128, 256>>>();

    // fork: CSR tail (scan2/scan3/place) overlaps conv
    cudaEventRecord(s_fork, 0);
    cudaStreamWaitEvent(s_side, s_fork, 0);
    scan2_kernel<<<1, 128, 0, s_side>>>();
    scan3_kernel<<<N_NODES / 256, 256, 0, s_side>>>();
    place_kernel<<<N_EDGES / 256, 256, 0, s_side>>>(e_row, e_col);
    cudaEventRecord(s_join, s_side);

    {
        dim3 gc(T4 / 128, BATCH);
        conv_mma_kernel<<<gc, 256, CV_SM_BYTES>>>(x, conv1_w, conv1_b, conv2_w, conv2_b);
    }

    cudaStreamWaitEvent(0, s_join, 0);

    gather32_kernel<<<N_NODES / 8, 256>>>();
    xw_mma_kernel<<<N_NODES / 128, 256>>>(gcn1_w, gcn1_b, gcn2_w);
    gather64_pool_kernel<<<N_NODES / 8, 256>>>(gcn2_b);
    cls_kernel<<<1, 640>>>(cls_w, cls_b, out);
}

// round 16
// speedup vs baseline: 1.4331x; 1.4331x over previous
#include <cuda_runtime.h>
#include <cuda_bf16.h>
#include <cuda_fp16.h>

// ---------------- problem constants ----------------
#define BATCH   64
#define T_IN    8192
#define T2      4096        // after pool1
#define T4      2048        // after pool2
#define N_NODES 131072      // BATCH * T4
#define N_EDGES 2097152
#define HID     64
#define OUTC    10

typedef unsigned long long u64;

// ---------------- f32x2 packed helpers (Blackwell) ----------------
__device__ __forceinline__ u64 pk2(float lo, float hi) {
    u64 r; asm("mov.b64 %0, {%1, %2};" : "=l"(r) : "f"(lo), "f"(hi)); return r;
}
__device__ __forceinline__ void upk2(u64 v, float& lo, float& hi) {
    asm("mov.b64 {%0, %1}, %2;" : "=f"(lo), "=f"(hi) : "l"(v));
}
__device__ __forceinline__ void fma2(u64& acc, u64 a, u64 b) {
    asm("fma.rn.f32x2 %0, %1, %2, %3;" : "=l"(acc) : "l"(a), "l"(b), "l"(acc));
}

// m16n8k16 fp16 MMA, fp32 accumulate (HMMA)
__device__ __forceinline__ void mma16816(float* d, const unsigned* a, const unsigned* b) {
    asm volatile(
        "mma.sync.aligned.m16n8k16.row.col.f32.f16.f16.f32 "
        "{%0,%1,%2,%3}, {%4,%5,%6,%7}, {%8,%9}, {%0,%1,%2,%3};"
        : "+f"(d[0]), "+f"(d[1]), "+f"(d[2]), "+f"(d[3])
        : "r"(a[0]), "r"(a[1]), "r"(a[2]), "r"(a[3]), "r"(b[0]), "r"(b[1]));
}

__device__ __forceinline__ unsigned h2u(__half2 h) { return *(unsigned*)&h; }

// ---------------- scratch (device globals, no allocation) ----------------
// NOTE: referenced ONLY inside device code (GB300 ATS silently reads the host
// shadow if passed as host-side kernel args).
__device__ __half2 g_feat_h[N_NODES * 16];       // conv2 out * dis, fp16, node-major
__device__ float   g_z[N_NODES * 32];            // aggregated 32-dim features (fp32)
__device__ __half2 g_y_h[N_NODES * 32];          // dis * (relu(z@W1+b1) @ W2), fp16
__device__ float   g_pool[BATCH * 64];           // per-batch channel sums
__device__ float   g_dis[N_NODES];
__device__ int     g_cnt[N_NODES];
__device__ int     g_off[N_NODES + 1];
__device__ int     g_cur[N_NODES];
__device__ int     g_srcs[N_EDGES];
__device__ int     g_bsum[128];

// ---------------- fused conv1+conv2+pools+dis -> fp16 node features ----------
// (R8/R10 proven version: fp32 sx, so-aliases-sx, 68 regs, 3 blocks/SM, FFMA2.)
#define SX_W   528
#define SX_V   524
#define SH1_W  264
#define SH1_V  260
#define SW1_N  (8 * 16 * 6)
#define SW2_N  (16 * 16 * 6)
#define SM_FLOATS (16*SX_W + 16*SH1_W + 16 + 32)
#define SM_BYTES  (SM_FLOATS*4 + (SW1_N + SW2_N)*8)

__global__ void conv_fused_kernel(const float* __restrict__ x,
                                  const float* __restrict__ w1,
                                  const float* __restrict__ b1,
                                  const float* __restrict__ w2,
                                  const float* __restrict__ b2) {
    extern __shared__ float sm[];
    float*   sx  = sm;                       // [16][SX_W]
    float*   sh1 = sm + 16 * SX_W;           // [16][SH1_W]
    float*   sb1 = sh1 + 16 * SH1_W;         // [16]
    float*   sb2 = sb1 + 16;                 // [32]
    u64*     sw1 = (u64*)(sb2 + 32);         // [SW1_N] stride-6 padded
    u64*     sw2 = sw1 + SW1_N;              // [SW2_N]
    __half2* so  = (__half2*)sm;             // ALIASES sx (dead in phase 2)

    const int tile = blockIdx.x, bb = blockIdx.y, tid = threadIdx.x;

    const int x0 = tile * 512 - 6;
    for (int i = tid; i < 16 * SX_V; i += 256) {
        int ci = i / SX_V, j = i - ci * SX_V;
        int t = x0 + j;
        sx[ci * SX_W + j] = (t >= 0 && t < T_IN) ? x[(bb * 16 + ci) * T_IN + t] : 0.f;
    }
    for (int i = tid; i < 8 * 16 * 5; i += 256) {
        int cp = i / 80, r = i - cp * 80;
        int ci = r / 5, k = r - ci * 5;
        sw1[(cp * 16 + ci) * 6 + k] = pk2(w1[(2 * cp) * 80 + r], w1[(2 * cp + 1) * 80 + r]);
    }
    for (int i = tid; i < 16 * 16 * 5; i += 256) {
        int cp = i / 80, r = i - cp * 80;
        int ci = r / 5, k = r - ci * 5;
        sw2[(cp * 16 + ci) * 6 + k] = pk2(w2[(2 * cp) * 80 + r], w2[(2 * cp + 1) * 80 + r]);
    }
    if (tid < 16) sb1[tid] = b1[tid];
    else if (tid < 48) sb2[tid - 16] = b2[tid - 16];
    __syncthreads();

    const int q0 = tile * 256 - 2;
    for (int j = tid; j < SH1_V; j += 256) {
        const int q = q0 + j;
        if (q < 0 || q >= T2) {
#pragma unroll
            for (int co = 0; co < 16; co++) sh1[co * SH1_W + j] = 0.f;
            continue;
        }
        const int px = 2 * j;
        u64 a0[8], a1[8];
#pragma unroll
        for (int cp = 0; cp < 8; cp++) { a0[cp] = 0ull; a1[cp] = 0ull; }
#pragma unroll
        for (int ci = 0; ci < 16; ci++) {
            const float2* sxp = (const float2*)&sx[ci * SX_W + px];
            float2 v01 = sxp[0], v23 = sxp[1], v45 = sxp[2];
            u64 x0p = pk2(v01.x, v01.x), x1p = pk2(v01.y, v01.y), x2p = pk2(v23.x, v23.x);
            u64 x3p = pk2(v23.y, v23.y), x4p = pk2(v45.x, v45.x), x5p = pk2(v45.y, v45.y);
#pragma unroll
            for (int cp = 0; cp < 8; cp++) {
                const u64* wp = &sw1[(cp * 16 + ci) * 6];
                ulonglong2 wA = *(const ulonglong2*)wp;
                ulonglong2 wB = *(const ulonglong2*)(wp + 2);
                u64 w4 = wp[4];
                fma2(a0[cp], wA.x, x0p); fma2(a1[cp], wA.x, x1p);
                fma2(a0[cp], wA.y, x1p); fma2(a1[cp], wA.y, x2p);
                fma2(a0[cp], wB.x, x2p); fma2(a1[cp], wB.x, x3p);
                fma2(a0[cp], wB.y, x3p); fma2(a1[cp], wB.y, x4p);
                fma2(a0[cp], w4,   x4p); fma2(a1[cp], w4,   x5p);
            }
        }
#pragma unroll
        for (int cp = 0; cp < 8; cp++) {
            float e0, o0, e1, o1;
            upk2(a0[cp], e0, o0);
            upk2(a1[cp], e1, o1);
            sh1[(2 * cp) * SH1_W + j]     = fmaxf(fmaxf(e0, e1) + sb1[2 * cp], 0.f);
            sh1[(2 * cp + 1) * SH1_W + j] = fmaxf(fmaxf(o0, o1) + sb1[2 * cp + 1], 0.f);
        }
    }
    __syncthreads();

    const int tp  = tid & 127;
    const int cob = tid >> 7;
    const int p0  = 2 * tp;

    u64 acc0[8], acc1[8];
#pragma unroll
    for (int q = 0; q < 8; q++) { acc0[q] = 0ull; acc1[q] = 0ull; }

#pragma unroll
    for (int ci = 0; ci < 16; ci++) {
        const float2* shp = (const float2*)&sh1[ci * SH1_W + p0];
        float2 v01 = shp[0], v23 = shp[1], v45 = shp[2];
        u64 x0p = pk2(v01.x, v01.x), x1p = pk2(v01.y, v01.y), x2p = pk2(v23.x, v23.x);
        u64 x3p = pk2(v23.y, v23.y), x4p = pk2(v45.x, v45.x), x5p = pk2(v45.y, v45.y);
#pragma unroll
        for (int q = 0; q < 8; q++) {
            const u64* wp = &sw2[((cob * 8 + q) * 16 + ci) * 6];
            ulonglong2 wA = *(const ulonglong2*)wp;
            ulonglong2 wB = *(const ulonglong2*)(wp + 2);
            u64 w4 = wp[4];
            fma2(acc0[q], wA.x, x0p); fma2(acc1[q], wA.x, x1p);
            fma2(acc0[q], wA.y, x1p); fma2(acc1[q], wA.y, x2p);
            fma2(acc0[q], wB.x, x2p); fma2(acc1[q], wB.x, x3p);
            fma2(acc0[q], wB.y, x3p); fma2(acc1[q], wB.y, x4p);
            fma2(acc0[q], w4,   x4p); fma2(acc1[q], w4,   x5p);
        }
    }

    const int node_base = bb * T4 + tile * 128;
    const float d = __ldg(&g_dis[node_base + tp]);
#pragma unroll
    for (int q = 0; q < 8; q++) {
        int cp = cob * 8 + q;
        float e0, o0, e1, o1;
        upk2(acc0[q], e0, o0);
        upk2(acc1[q], e1, o1);
        float re = fmaxf(fmaxf(e0, e1) + sb2[2 * cp], 0.f) * d;
        float ro = fmaxf(fmaxf(o0, o1) + sb2[2 * cp + 1], 0.f) * d;
        so[tp * 17 + cp] = __floats2half2_rn(re, ro);
    }
    __syncthreads();

    for (int i = tid; i < 128 * 16; i += 256) {
        int lp = i >> 4, c = i & 15;
        g_feat_h[(node_base + lp) * 16 + c] = so[lp * 17 + c];
    }
}

// ---------------- CSR build ----------------
__global__ void zero_cnt_kernel() {
    int i = blockIdx.x * blockDim.x + threadIdx.x;
    if (i < N_NODES) g_cnt[i] = 0;
    if (i < BATCH * 64) g_pool[i] = 0.f;
}

__global__ void hist_kernel(const int* __restrict__ col) {
    int e = blockIdx.x * blockDim.x + threadIdx.x;
    if (e < N_EDGES) atomicAdd(&g_cnt[col[e]], 1);
}

__global__ void scan1_kernel() {
    __shared__ int ss[256];
    const int tid = threadIdx.x;
    const int base = blockIdx.x * 1024 + tid * 4;
    int v0 = g_cnt[base], v1 = g_cnt[base + 1], v2 = g_cnt[base + 2], v3 = g_cnt[base + 3];
    g_dis[base]     = rsqrtf((float)(v0 + 1));
    g_dis[base + 1] = rsqrtf((float)(v1 + 1));
    g_dis[base + 2] = rsqrtf((float)(v2 + 1));
    g_dis[base + 3] = rsqrtf((float)(v3 + 1));
    int tsum = v0 + v1 + v2 + v3;
    ss[tid] = tsum;
    __syncthreads();
    for (int d = 1; d < 256; d <<= 1) {
        int t = (tid >= d) ? ss[tid - d] : 0;
        __syncthreads();
        ss[tid] += t;
        __syncthreads();
    }
    int excl = ss[tid] - tsum;
    g_off[base]     = excl;
    g_off[base + 1] = excl + v0;
    g_off[base + 2] = excl + v0 + v1;
    g_off[base + 3] = excl + v0 + v1 + v2;
    if (tid == 255) g_bsum[blockIdx.x] = ss[255];
}

__global__ void scan2_kernel() {
    __shared__ int ss[128];
    const int tid = threadIdx.x;
    int v = g_bsum[tid];
    ss[tid] = v;
    __syncthreads();
    for (int d = 1; d < 128; d <<= 1) {
        int t = (tid >= d) ? ss[tid - d] : 0;
        __syncthreads();
        ss[tid] += t;
        __syncthreads();
    }
    g_bsum[tid] = ss[tid] - v;
}

__global__ void scan3_kernel() {
    int i = blockIdx.x * blockDim.x + threadIdx.x;
    if (i < N_NODES) {
        int o = g_off[i] + g_bsum[i >> 10];
        g_off[i] = o;
        g_cur[i] = o;
        if (i == 0) g_off[N_NODES] = N_EDGES;
    }
}

__global__ void place_kernel(const int* __restrict__ row, const int* __restrict__ col) {
    int e = blockIdx.x * blockDim.x + threadIdx.x;
    if (e < N_EDGES) {
        int c = col[e];
        int p = atomicAdd(&g_cur[c], 1);
        g_srcs[p] = row[e];
    }
}

// ---------------- gather32 (fp16): z[i] = dis_i * (feat~[i] + sum feat~[j]) ----
__global__ void gather32_kernel() {
    const int gw = (blockIdx.x * 256 + threadIdx.x) >> 5;
    const int lane = threadIdx.x & 31;
    const int hw = lane >> 4, c = lane & 15;
    const __half2* __restrict__ y = g_feat_h;

    float ax = 0.f, ay = 0.f;
    int p = g_off[gw];
    const int e = g_off[gw + 1];
    for (; p + 8 <= e; p += 8) {
        int j0 = __ldg(&g_srcs[p + 0 + hw]);
        int j1 = __ldg(&g_srcs[p + 2 + hw]);
        int j2 = __ldg(&g_srcs[p + 4 + hw]);
        int j3 = __ldg(&g_srcs[p + 6 + hw]);
        float2 v0 = __half22float2(__ldg(&y[j0 * 16 + c]));
        float2 v1 = __half22float2(__ldg(&y[j1 * 16 + c]));
        float2 v2 = __half22float2(__ldg(&y[j2 * 16 + c]));
        float2 v3 = __half22float2(__ldg(&y[j3 * 16 + c]));
        ax += (v0.x + v1.x) + (v2.x + v3.x);
        ay += (v0.y + v1.y) + (v2.y + v3.y);
    }
    for (; p + 2 <= e; p += 2) {
        int j = __ldg(&g_srcs[p + hw]);
        float2 v = __half22float2(__ldg(&y[j * 16 + c]));
        ax += v.x; ay += v.y;
    }
    if (p < e && hw == 0) {
        int j = __ldg(&g_srcs[p]);
        float2 v = __half22float2(__ldg(&y[j * 16 + c]));
        ax += v.x; ay += v.y;
    }
    ax += __shfl_xor_sync(0xFFFFFFFFu, ax, 16);
    ay += __shfl_xor_sync(0xFFFFFFFFu, ay, 16);
    if (lane < 16) {
        float2 self = __half22float2(__ldg(&y[gw * 16 + c]));
        const float d = g_dis[gw];
        float2 r;
        r.x = (self.x + ax) * d;
        r.y = (self.y + ay) * d;
        ((float2*)g_z)[gw * 16 + c] = r;
    }
}

// ---------------- xw via tensor cores (HMMA, hi/lo weight split) -------------
__global__ void __launch_bounds__(256)
xw_mma_kernel(const float* __restrict__ W1,
              const float* __restrict__ b1,
              const float* __restrict__ W2) {
    __shared__ __align__(16) __half sW1h[64 * 40];   // [n][k], stride 40
    __shared__ __align__(16) __half sW1l[64 * 40];
    __shared__ __align__(16) __half sW2h[64 * 72];   // [n][k], stride 72
    __shared__ __align__(16) __half sW2l[64 * 72];
    __shared__ float sb1v[64];
    __shared__ __align__(16) __half sH[8][16 * 72];  // per-warp h, row stride 72

    const int tid = threadIdx.x;
    for (int i = tid; i < 32 * 64; i += 256) {
        int k = i >> 6, n = i & 63;
        float v = W1[i];
        __half hi = __float2half_rn(v);
        sW1h[n * 40 + k] = hi;
        sW1l[n * 40 + k] = __float2half_rn(v - __half2float(hi));
    }
    for (int i = tid; i < 64 * 64; i += 256) {
        int k = i >> 6, n = i & 63;
        float v = W2[i];
        __half hi = __float2half_rn(v);
        sW2h[n * 72 + k] = hi;
        sW2l[n * 72 + k] = __float2half_rn(v - __half2float(hi));
    }
    if (tid < 64) sb1v[tid] = b1[tid];
    __syncthreads();

    const int w = tid >> 5, lane = tid & 31;
    const int g = lane >> 2, t = lane & 3;
    const int nb = blockIdx.x * 128 + w * 16;
    __half* H = &sH[w][0];

    // ---- stage 1: C1[16x64] = A(z)[16x32] @ W1[32x64] ----
    float acc[8][4];
#pragma unroll
    for (int nf = 0; nf < 8; nf++)
#pragma unroll
        for (int q = 0; q < 4; q++) acc[nf][q] = 0.f;

#pragma unroll
    for (int kf = 0; kf < 2; kf++) {
        const int k0 = kf * 16;
        unsigned a[4];
        {
            float2 v;
            v = *(const float2*)&g_z[(size_t)(nb + g) * 32 + k0 + 2 * t];
            __half2 h = __floats2half2_rn(v.x, v.y); a[0] = h2u(h);
            v = *(const float2*)&g_z[(size_t)(nb + g + 8) * 32 + k0 + 2 * t];
            h = __floats2half2_rn(v.x, v.y); a[1] = h2u(h);
            v = *(const float2*)&g_z[(size_t)(nb + g) * 32 + k0 + 2 * t + 8];
            h = __floats2half2_rn(v.x, v.y); a[2] = h2u(h);
            v = *(const float2*)&g_z[(size_t)(nb + g + 8) * 32 + k0 + 2 * t + 8];
            h = __floats2half2_rn(v.x, v.y); a[3] = h2u(h);
        }
#pragma unroll
        for (int nf = 0; nf < 8; nf++) {
            unsigned bv[2];
            bv[0] = *(const unsigned*)&sW1h[(nf * 8 + g) * 40 + k0 + 2 * t];
            bv[1] = *(const unsigned*)&sW1h[(nf * 8 + g) * 40 + k0 + 2 * t + 8];
            mma16816(acc[nf], a, bv);
            bv[0] = *(const unsigned*)&sW1l[(nf * 8 + g) * 40 + k0 + 2 * t];
            bv[1] = *(const unsigned*)&sW1l[(nf * 8 + g) * 40 + k0 + 2 * t + 8];
            mma16816(acc[nf], a, bv);
        }
    }

    // ---- bias + relu -> fp16 staging ----
#pragma unroll
    for (int nf = 0; nf < 8; nf++) {
        const int c0 = nf * 8 + 2 * t;
        float h0 = fmaxf(acc[nf][0] + sb1v[c0],     0.f);
        float h1 = fmaxf(acc[nf][1] + sb1v[c0 + 1], 0.f);
        float h2 = fmaxf(acc[nf][2] + sb1v[c0],     0.f);
        float h3 = fmaxf(acc[nf][3] + sb1v[c0 + 1], 0.f);
        *(__half2*)&H[g * 72 + c0]       = __floats2half2_rn(h0, h1);
        *(__half2*)&H[(g + 8) * 72 + c0] = __floats2half2_rn(h2, h3);
    }
    __syncwarp();

    // ---- stage 2: C2[16x64] = h[16x64] @ W2[64x64] ----
    float acc2[8][4];
#pragma unroll
    for (int nf = 0; nf < 8; nf++)
#pragma unroll
        for (int q = 0; q < 4; q++) acc2[nf][q] = 0.f;

#pragma unroll
    for (int kf = 0; kf < 4; kf++) {
        const int k0 = kf * 16;
        unsigned a[4];
        a[0] = *(const unsigned*)&H[g * 72 + k0 + 2 * t];
        a[1] = *(const unsigned*)&H[(g + 8) * 72 + k0 + 2 * t];
        a[2] = *(const unsigned*)&H[g * 72 + k0 + 2 * t + 8];
        a[3] = *(const unsigned*)&H[(g + 8) * 72 + k0 + 2 * t + 8];
#pragma unroll
        for (int nf = 0; nf < 8; nf++) {
            unsigned bv[2];
            bv[0] = *(const unsigned*)&sW2h[(nf * 8 + g) * 72 + k0 + 2 * t];
            bv[1] = *(const unsigned*)&sW2h[(nf * 8 + g) * 72 + k0 + 2 * t + 8];
            mma16816(acc2[nf], a, bv);
            bv[0] = *(const unsigned*)&sW2l[(nf * 8 + g) * 72 + k0 + 2 * t];
            bv[1] = *(const unsigned*)&sW2l[(nf * 8 + g) * 72 + k0 + 2 * t + 8];
            mma16816(acc2[nf], a, bv);
        }
    }

    // ---- dis scale + fp16 write ----
    const float d0 = g_dis[nb + g], d1 = g_dis[nb + g + 8];
    __half2* y0 = g_y_h + (size_t)(nb + g) * 32;
    __half2* y1 = g_y_h + (size_t)(nb + g + 8) * 32;
#pragma unroll
    for (int nf = 0; nf < 8; nf++) {
        const int cw = nf * 4 + t;
        y0[cw] = __floats2half2_rn(acc2[nf][0] * d0, acc2[nf][1] * d0);
        y1[cw] = __floats2half2_rn(acc2[nf][2] * d1, acc2[nf][3] * d1);
    }
}

// ---------------- gather64 + fused mean-pool partial reduction ----------------
__global__ void gather64_pool_kernel(const float* __restrict__ bias) {
    __shared__ float pool[64];
    const __half2* __restrict__ y = g_y_h;
    const int tid = threadIdx.x;
    const int gw = (blockIdx.x * 256 + tid) >> 5;
    const int lane = tid & 31;
    if (tid < 64) pool[tid] = 0.f;
    __syncthreads();

    float2 a = __half22float2(__ldg(&y[gw * 32 + lane]));
    int p = g_off[gw];
    const int e = g_off[gw + 1];
    for (; p + 16 <= e; p += 16) {
        int jj[16];
#pragma unroll
        for (int u = 0; u < 16; u++) jj[u] = __ldg(&g_srcs[p + u]);
        float2 vv[16];
#pragma unroll
        for (int u = 0; u < 16; u++) vv[u] = __half22float2(__ldg(&y[jj[u] * 32 + lane]));
        float sx0 = 0.f, sy0 = 0.f;
#pragma unroll
        for (int u = 0; u < 16; u++) { sx0 += vv[u].x; sy0 += vv[u].y; }
        a.x += sx0; a.y += sy0;
    }
    for (; p + 4 <= e; p += 4) {
        int j0 = __ldg(&g_srcs[p + 0]), j1 = __ldg(&g_srcs[p + 1]);
        int j2 = __ldg(&g_srcs[p + 2]), j3 = __ldg(&g_srcs[p + 3]);
        float2 v0 = __half22float2(__ldg(&y[j0 * 32 + lane]));
        float2 v1 = __half22float2(__ldg(&y[j1 * 32 + lane]));
        float2 v2 = __half22float2(__ldg(&y[j2 * 32 + lane]));
        float2 v3 = __half22float2(__ldg(&y[j3 * 32 + lane]));
        a.x += (v0.x + v1.x) + (v2.x + v3.x);
        a.y += (v0.y + v1.y) + (v2.y + v3.y);
    }
    for (; p < e; p++) {
        int j = __ldg(&g_srcs[p]);
        float2 v = __half22float2(__ldg(&y[j * 32 + lane]));
        a.x += v.x; a.y += v.y;
    }
    const float d = g_dis[gw];
    float2 bb = ((const float2*)bias)[lane];
    float rx = fmaxf(fmaf(d, a.x, bb.x), 0.f);
    float ry = fmaxf(fmaf(d, a.y, bb.y), 0.f);
    atomicAdd(&pool[2 * lane],     rx);
    atomicAdd(&pool[2 * lane + 1], ry);
    __syncthreads();
    if (tid < 64) {
        const int batch = gw >> 11;
        atomicAdd(&g_pool[batch * 64 + tid], pool[tid]);
    }
}

// ---------------- classifier from pooled sums ----------------
__global__ void cls_kernel(const float* __restrict__ clsw,
                           const float* __restrict__ clsb,
                           float* __restrict__ out) {
    __shared__ float sw[64 * OUTC];
    const int tid = threadIdx.x;
    if (tid < 64 * OUTC) sw[tid] = clsw[tid];
    __syncthreads();
    if (tid < BATCH * OUTC) {
        const int b = tid / OUTC, o = tid - b * OUTC;
        float acc = clsb[o];
#pragma unroll
        for (int c = 0; c < 64; c++)
            acc += g_pool[b * 64 + c] * sw[c * OUTC + o];
        out[tid] = acc * (1.f / (float)T4) + clsb[o] * (1.f - 1.f / (float)T4);
    }
}

// ---------------- launch ----------------
extern "C" void kernel_launch(void* const* d_in, const int* in_sizes, int n_in,
                              void* d_out, int out_size) {
    const float* x       = nullptr;
    const int*   ei      = nullptr;
    const float* conv1_w = nullptr; const float* conv1_b = nullptr;
    const float* conv2_w = nullptr; const float* conv2_b = nullptr;
    const float* gcn1_w  = nullptr; const float* gcn1_b  = nullptr;
    const float* gcn2_w  = nullptr; const float* gcn2_b  = nullptr;
    const float* cls_w   = nullptr; const float* cls_b   = nullptr;

    for (int i = 0; i < n_in; i++) {
        switch (in_sizes[i]) {
            case BATCH * 16 * T_IN:   x       = (const float*)d_in[i]; break;
            case 2 * N_EDGES:         ei      = (const int*)  d_in[i]; break;
            case 16 * 16 * 5:         conv1_w = (const float*)d_in[i]; break;
            case 16:                  conv1_b = (const float*)d_in[i]; break;
            case 32 * 16 * 5:         conv2_w = (const float*)d_in[i]; break;
            case 32:                  conv2_b = (const float*)d_in[i]; break;
            case 32 * HID:            gcn1_w  = (const float*)d_in[i]; break;
            case HID * HID:           gcn2_w  = (const float*)d_in[i]; break;
            case HID * OUTC:          cls_w   = (const float*)d_in[i]; break;
            case OUTC:                cls_b   = (const float*)d_in[i]; break;
            case HID:
                if (!gcn1_b) gcn1_b = (const float*)d_in[i];
                else         gcn2_b = (const float*)d_in[i];
                break;
            default: break;
        }
    }
    if (!x || !ei || !conv1_w || !conv2_w || !gcn1_w || !gcn2_w || !cls_w) {
        x       = (const float*)d_in[0];  ei      = (const int*)  d_in[1];
        conv1_w = (const float*)d_in[2];  conv1_b = (const float*)d_in[3];
        conv2_w = (const float*)d_in[4];  conv2_b = (const float*)d_in[5];
        gcn1_w  = (const float*)d_in[6];  gcn1_b  = (const float*)d_in[7];
        gcn2_w  = (const float*)d_in[8];  gcn2_b  = (const float*)d_in[9];
        cls_w   = (const float*)d_in[10]; cls_b   = (const float*)d_in[11];
    }

    float* out = (float*)d_out;
    const int* e_row = ei;
    const int* e_col = ei + N_EDGES;

    cudaFuncSetAttribute(conv_fused_kernel,
                         cudaFuncAttributeMaxDynamicSharedMemorySize, SM_BYTES);

    static cudaStream_t s_side = nullptr;
    static cudaEvent_t  s_fork = nullptr, s_join = nullptr;
    if (!s_side) {
        cudaStreamCreateWithFlags(&s_side, cudaStreamNonBlocking);
        cudaEventCreateWithFlags(&s_fork, cudaEventDisableTiming);
        cudaEventCreateWithFlags(&s_join, cudaEventDisableTiming);
    }

    // shared prefix: counts + dis (conv needs dis; CSR tail needs counts)
    zero_cnt_kernel<<<N_NODES / 256, 256>>>();
    hist_kernel<<<N_EDGES / 256, 256>>>(e_col);
    scan1_kernel<<<128, 256>>>();

    // fork: CSR tail (scan2/scan3/place) overlaps conv
    cudaEventRecord(s_fork, 0);
    cudaStreamWaitEvent(s_side, s_fork, 0);
    scan2_kernel<<<1, 128, 0, s_side>>>();
    scan3_kernel<<<N_NODES / 256, 256, 0, s_side>>>();
    place_kernel<<<N_EDGES / 256, 256, 0, s_side>>>(e_row, e_col);
    cudaEventRecord(s_join, s_side);

    {
        dim3 gc(T4 / 128, BATCH);
        conv_fused_kernel<<<gc, 256, SM_BYTES>>>(x, conv1_w, conv1_b, conv2_w, conv2_b);
    }

    cudaStreamWaitEvent(0, s_join, 0);

    gather32_kernel<<<N_NODES / 8, 256>>>();
    xw_mma_kernel<<<N_NODES / 128, 256>>>(gcn1_w, gcn1_b, gcn2_w);
    gather64_pool_kernel<<<N_NODES / 8, 256>>>(gcn2_b);
    cls_kernel<<<1, 640>>>(cls_w, cls_b, out);
}

// round 17
// speedup vs baseline: 1.4379x; 1.0033x over previous
#include <cuda_runtime.h>
#include <cuda_bf16.h>
#include <cuda_fp16.h>

// ---------------- problem constants ----------------
#define BATCH   64
#define T_IN    8192
#define T2      4096        // after pool1
#define T4      2048        // after pool2
#define N_NODES 131072      // BATCH * T4
#define N_EDGES 2097152
#define HID     64
#define OUTC    10

typedef unsigned long long u64;

// ---------------- f32x2 packed helpers (Blackwell) ----------------
__device__ __forceinline__ u64 pk2(float lo, float hi) {
    u64 r; asm("mov.b64 %0, {%1, %2};" : "=l"(r) : "f"(lo), "f"(hi)); return r;
}
__device__ __forceinline__ void upk2(u64 v, float& lo, float& hi) {
    asm("mov.b64 {%0, %1}, %2;" : "=f"(lo), "=f"(hi) : "l"(v));
}
__device__ __forceinline__ void fma2(u64& acc, u64 a, u64 b) {
    asm("fma.rn.f32x2 %0, %1, %2, %3;" : "=l"(acc) : "l"(a), "l"(b), "l"(acc));
}

// m16n8k16 fp16 MMA, fp32 accumulate (HMMA)
__device__ __forceinline__ void mma16816(float* d, const unsigned* a, const unsigned* b) {
    asm volatile(
        "mma.sync.aligned.m16n8k16.row.col.f32.f16.f16.f32 "
        "{%0,%1,%2,%3}, {%4,%5,%6,%7}, {%8,%9}, {%0,%1,%2,%3};"
        : "+f"(d[0]), "+f"(d[1]), "+f"(d[2]), "+f"(d[3])
        : "r"(a[0]), "r"(a[1]), "r"(a[2]), "r"(a[3]), "r"(b[0]), "r"(b[1]));
}

__device__ __forceinline__ unsigned h2u(__half2 h) { return *(unsigned*)&h; }

// ---------------- scratch (device globals, no allocation) ----------------
// NOTE: referenced ONLY inside device code (GB300 ATS silently reads the host
// shadow if passed as host-side kernel args).
__device__ __half2 g_feat_h[N_NODES * 16];       // conv2 out * dis, fp16, node-major
__device__ __half2 g_z_h[N_NODES * 16];          // aggregated 32-dim features, fp16
__device__ __half2 g_y_h[N_NODES * 32];          // dis * (relu(z@W1+b1) @ W2), fp16
__device__ float   g_pool[BATCH * 64];           // per-batch channel sums
__device__ float   g_dis[N_NODES];
__device__ int     g_cnt[N_NODES];
__device__ int     g_off[N_NODES + 1];
__device__ int     g_cur[N_NODES];
__device__ int     g_srcs[N_EDGES];
__device__ int     g_bsum[128];

// ---------------- fused conv1+conv2+pools+dis -> fp16 node features ----------
// R8/R10 proven FFMA2 version. dis computed in-epilogue from g_cnt, so conv
// depends only on hist (scan1 runs on the side stream).
#define SX_W   528
#define SX_V   524
#define SH1_W  264
#define SH1_V  260
#define SW1_N  (8 * 16 * 6)
#define SW2_N  (16 * 16 * 6)
#define SM_FLOATS (16*SX_W + 16*SH1_W + 16 + 32)
#define SM_BYTES  (SM_FLOATS*4 + (SW1_N + SW2_N)*8)

__global__ void conv_fused_kernel(const float* __restrict__ x,
                                  const float* __restrict__ w1,
                                  const float* __restrict__ b1,
                                  const float* __restrict__ w2,
                                  const float* __restrict__ b2) {
    extern __shared__ float sm[];
    float*   sx  = sm;                       // [16][SX_W]
    float*   sh1 = sm + 16 * SX_W;           // [16][SH1_W]
    float*   sb1 = sh1 + 16 * SH1_W;         // [16]
    float*   sb2 = sb1 + 16;                 // [32]
    u64*     sw1 = (u64*)(sb2 + 32);         // [SW1_N] stride-6 padded
    u64*     sw2 = sw1 + SW1_N;              // [SW2_N]
    __half2* so  = (__half2*)sm;             // ALIASES sx (dead in phase 2)

    const int tile = blockIdx.x, bb = blockIdx.y, tid = threadIdx.x;

    const int x0 = tile * 512 - 6;
    for (int i = tid; i < 16 * SX_V; i += 256) {
        int ci = i / SX_V, j = i - ci * SX_V;
        int t = x0 + j;
        sx[ci * SX_W + j] = (t >= 0 && t < T_IN) ? x[(bb * 16 + ci) * T_IN + t] : 0.f;
    }
    for (int i = tid; i < 8 * 16 * 5; i += 256) {
        int cp = i / 80, r = i - cp * 80;
        int ci = r / 5, k = r - ci * 5;
        sw1[(cp * 16 + ci) * 6 + k] = pk2(w1[(2 * cp) * 80 + r], w1[(2 * cp + 1) * 80 + r]);
    }
    for (int i = tid; i < 16 * 16 * 5; i += 256) {
        int cp = i / 80, r = i - cp * 80;
        int ci = r / 5, k = r - ci * 5;
        sw2[(cp * 16 + ci) * 6 + k] = pk2(w2[(2 * cp) * 80 + r], w2[(2 * cp + 1) * 80 + r]);
    }
    if (tid < 16) sb1[tid] = b1[tid];
    else if (tid < 48) sb2[tid - 16] = b2[tid - 16];
    __syncthreads();

    const int q0 = tile * 256 - 2;
    for (int j = tid; j < SH1_V; j += 256) {
        const int q = q0 + j;
        if (q < 0 || q >= T2) {
#pragma unroll
            for (int co = 0; co < 16; co++) sh1[co * SH1_W + j] = 0.f;
            continue;
        }
        const int px = 2 * j;
        u64 a0[8], a1[8];
#pragma unroll
        for (int cp = 0; cp < 8; cp++) { a0[cp] = 0ull; a1[cp] = 0ull; }
#pragma unroll
        for (int ci = 0; ci < 16; ci++) {
            const float2* sxp = (const float2*)&sx[ci * SX_W + px];
            float2 v01 = sxp[0], v23 = sxp[1], v45 = sxp[2];
            u64 x0p = pk2(v01.x, v01.x), x1p = pk2(v01.y, v01.y), x2p = pk2(v23.x, v23.x);
            u64 x3p = pk2(v23.y, v23.y), x4p = pk2(v45.x, v45.x), x5p = pk2(v45.y, v45.y);
#pragma unroll
            for (int cp = 0; cp < 8; cp++) {
                const u64* wp = &sw1[(cp * 16 + ci) * 6];
                ulonglong2 wA = *(const ulonglong2*)wp;
                ulonglong2 wB = *(const ulonglong2*)(wp + 2);
                u64 w4 = wp[4];
                fma2(a0[cp], wA.x, x0p); fma2(a1[cp], wA.x, x1p);
                fma2(a0[cp], wA.y, x1p); fma2(a1[cp], wA.y, x2p);
                fma2(a0[cp], wB.x, x2p); fma2(a1[cp], wB.x, x3p);
                fma2(a0[cp], wB.y, x3p); fma2(a1[cp], wB.y, x4p);
                fma2(a0[cp], w4,   x4p); fma2(a1[cp], w4,   x5p);
            }
        }
#pragma unroll
        for (int cp = 0; cp < 8; cp++) {
            float e0, o0, e1, o1;
            upk2(a0[cp], e0, o0);
            upk2(a1[cp], e1, o1);
            sh1[(2 * cp) * SH1_W + j]     = fmaxf(fmaxf(e0, e1) + sb1[2 * cp], 0.f);
            sh1[(2 * cp + 1) * SH1_W + j] = fmaxf(fmaxf(o0, o1) + sb1[2 * cp + 1], 0.f);
        }
    }
    __syncthreads();

    const int tp  = tid & 127;
    const int cob = tid >> 7;
    const int p0  = 2 * tp;

    u64 acc0[8], acc1[8];
#pragma unroll
    for (int q = 0; q < 8; q++) { acc0[q] = 0ull; acc1[q] = 0ull; }

#pragma unroll
    for (int ci = 0; ci < 16; ci++) {
        const float2* shp = (const float2*)&sh1[ci * SH1_W + p0];
        float2 v01 = shp[0], v23 = shp[1], v45 = shp[2];
        u64 x0p = pk2(v01.x, v01.x), x1p = pk2(v01.y, v01.y), x2p = pk2(v23.x, v23.x);
        u64 x3p = pk2(v23.y, v23.y), x4p = pk2(v45.x, v45.x), x5p = pk2(v45.y, v45.y);
#pragma unroll
        for (int q = 0; q < 8; q++) {
            const u64* wp = &sw2[((cob * 8 + q) * 16 + ci) * 6];
            ulonglong2 wA = *(const ulonglong2*)wp;
            ulonglong2 wB = *(const ulonglong2*)(wp + 2);
            u64 w4 = wp[4];
            fma2(acc0[q], wA.x, x0p); fma2(acc1[q], wA.x, x1p);
            fma2(acc0[q], wA.y, x1p); fma2(acc1[q], wA.y, x2p);
            fma2(acc0[q], wB.x, x2p); fma2(acc1[q], wB.x, x3p);
            fma2(acc0[q], wB.y, x3p); fma2(acc1[q], wB.y, x4p);
            fma2(acc0[q], w4,   x4p); fma2(acc1[q], w4,   x5p);
        }
    }

    const int node_base = bb * T4 + tile * 128;
    const float d = rsqrtf((float)(__ldg(&g_cnt[node_base + tp]) + 1));  // dis from counts
#pragma unroll
    for (int q = 0; q < 8; q++) {
        int cp = cob * 8 + q;
        float e0, o0, e1, o1;
        upk2(acc0[q], e0, o0);
        upk2(acc1[q], e1, o1);
        float re = fmaxf(fmaxf(e0, e1) + sb2[2 * cp], 0.f) * d;
        float ro = fmaxf(fmaxf(o0, o1) + sb2[2 * cp + 1], 0.f) * d;
        so[tp * 17 + cp] = __floats2half2_rn(re, ro);
    }
    __syncthreads();

    for (int i = tid; i < 128 * 16; i += 256) {
        int lp = i >> 4, c = i & 15;
        g_feat_h[(node_base + lp) * 16 + c] = so[lp * 17 + c];
    }
}

// ---------------- CSR build ----------------
__global__ void zero_cnt_kernel() {
    int i = blockIdx.x * blockDim.x + threadIdx.x;
    if (i < N_NODES) g_cnt[i] = 0;
    if (i < BATCH * 64) g_pool[i] = 0.f;
}

__global__ void hist_kernel(const int* __restrict__ col) {
    int e = blockIdx.x * blockDim.x + threadIdx.x;
    if (e < N_EDGES) atomicAdd(&g_cnt[col[e]], 1);
}

__global__ void scan1_kernel() {
    __shared__ int ss[256];
    const int tid = threadIdx.x;
    const int base = blockIdx.x * 1024 + tid * 4;
    int v0 = g_cnt[base], v1 = g_cnt[base + 1], v2 = g_cnt[base + 2], v3 = g_cnt[base + 3];
    g_dis[base]     = rsqrtf((float)(v0 + 1));
    g_dis[base + 1] = rsqrtf((float)(v1 + 1));
    g_dis[base + 2] = rsqrtf((float)(v2 + 1));
    g_dis[base + 3] = rsqrtf((float)(v3 + 1));
    int tsum = v0 + v1 + v2 + v3;
    ss[tid] = tsum;
    __syncthreads();
    for (int d = 1; d < 256; d <<= 1) {
        int t = (tid >= d) ? ss[tid - d] : 0;
        __syncthreads();
        ss[tid] += t;
        __syncthreads();
    }
    int excl = ss[tid] - tsum;
    g_off[base]     = excl;
    g_off[base + 1] = excl + v0;
    g_off[base + 2] = excl + v0 + v1;
    g_off[base + 3] = excl + v0 + v1 + v2;
    if (tid == 255) g_bsum[blockIdx.x] = ss[255];
}

__global__ void scan2_kernel() {
    __shared__ int ss[128];
    const int tid = threadIdx.x;
    int v = g_bsum[tid];
    ss[tid] = v;
    __syncthreads();
    for (int d = 1; d < 128; d <<= 1) {
        int t = (tid >= d) ? ss[tid - d] : 0;
        __syncthreads();
        ss[tid] += t;
        __syncthreads();
    }
    g_bsum[tid] = ss[tid] - v;
}

__global__ void scan3_kernel() {
    int i = blockIdx.x * blockDim.x + threadIdx.x;
    if (i < N_NODES) {
        int o = g_off[i] + g_bsum[i >> 10];
        g_off[i] = o;
        g_cur[i] = o;
        if (i == 0) g_off[N_NODES] = N_EDGES;
    }
}

__global__ void place_kernel(const int* __restrict__ row, const int* __restrict__ col) {
    int e = blockIdx.x * blockDim.x + threadIdx.x;
    if (e < N_EDGES) {
        int c = col[e];
        int p = atomicAdd(&g_cur[c], 1);
        g_srcs[p] = row[e];
    }
}

// ---------------- gather32 (fp16 in, fp16 out) -------------------------------
// z[i] = dis_i * (feat~[i] + sum feat~[j]); feat~ already dis-scaled.
__global__ void gather32_kernel() {
    const int gw = (blockIdx.x * 256 + threadIdx.x) >> 5;
    const int lane = threadIdx.x & 31;
    const int hw = lane >> 4, c = lane & 15;
    const __half2* __restrict__ y = g_feat_h;

    float ax = 0.f, ay = 0.f;
    int p = g_off[gw];
    const int e = g_off[gw + 1];
    for (; p + 8 <= e; p += 8) {
        int j0 = __ldg(&g_srcs[p + 0 + hw]);
        int j1 = __ldg(&g_srcs[p + 2 + hw]);
        int j2 = __ldg(&g_srcs[p + 4 + hw]);
        int j3 = __ldg(&g_srcs[p + 6 + hw]);
        float2 v0 = __half22float2(__ldg(&y[j0 * 16 + c]));
        float2 v1 = __half22float2(__ldg(&y[j1 * 16 + c]));
        float2 v2 = __half22float2(__ldg(&y[j2 * 16 + c]));
        float2 v3 = __half22float2(__ldg(&y[j3 * 16 + c]));
        ax += (v0.x + v1.x) + (v2.x + v3.x);
        ay += (v0.y + v1.y) + (v2.y + v3.y);
    }
    for (; p + 2 <= e; p += 2) {
        int j = __ldg(&g_srcs[p + hw]);
        float2 v = __half22float2(__ldg(&y[j * 16 + c]));
        ax += v.x; ay += v.y;
    }
    if (p < e && hw == 0) {
        int j = __ldg(&g_srcs[p]);
        float2 v = __half22float2(__ldg(&y[j * 16 + c]));
        ax += v.x; ay += v.y;
    }
    ax += __shfl_xor_sync(0xFFFFFFFFu, ax, 16);
    ay += __shfl_xor_sync(0xFFFFFFFFu, ay, 16);
    if (lane < 16) {
        float2 self = __half22float2(__ldg(&y[gw * 16 + c]));
        const float d = g_dis[gw];
        g_z_h[gw * 16 + c] = __floats2half2_rn((self.x + ax) * d, (self.y + ay) * d);
    }
}

// ---------------- xw via tensor cores (HMMA, hi/lo weight split) -------------
__global__ void __launch_bounds__(256)
xw_mma_kernel(const float* __restrict__ W1,
              const float* __restrict__ b1,
              const float* __restrict__ W2) {
    __shared__ __align__(16) __half sW1h[64 * 40];   // [n][k], stride 40
    __shared__ __align__(16) __half sW1l[64 * 40];
    __shared__ __align__(16) __half sW2h[64 * 72];   // [n][k], stride 72
    __shared__ __align__(16) __half sW2l[64 * 72];
    __shared__ float sb1v[64];
    __shared__ __align__(16) __half sH[8][16 * 72];  // per-warp h, row stride 72

    const int tid = threadIdx.x;
    for (int i = tid; i < 32 * 64; i += 256) {
        int k = i >> 6, n = i & 63;
        float v = W1[i];
        __half hi = __float2half_rn(v);
        sW1h[n * 40 + k] = hi;
        sW1l[n * 40 + k] = __float2half_rn(v - __half2float(hi));
    }
    for (int i = tid; i < 64 * 64; i += 256) {
        int k = i >> 6, n = i & 63;
        float v = W2[i];
        __half hi = __float2half_rn(v);
        sW2h[n * 72 + k] = hi;
        sW2l[n * 72 + k] = __float2half_rn(v - __half2float(hi));
    }
    if (tid < 64) sb1v[tid] = b1[tid];
    __syncthreads();

    const int w = tid >> 5, lane = tid & 31;
    const int g = lane >> 2, t = lane & 3;
    const int nb = blockIdx.x * 128 + w * 16;
    __half* H = &sH[w][0];

    // ---- stage 1: C1[16x64] = A(z fp16)[16x32] @ W1[32x64] ----
    float acc[8][4];
#pragma unroll
    for (int nf = 0; nf < 8; nf++)
#pragma unroll
        for (int q = 0; q < 4; q++) acc[nf][q] = 0.f;

#pragma unroll
    for (int kf = 0; kf < 2; kf++) {
        const int k0h = kf * 8;          // half2 index base (k0 elements / 2)
        unsigned a[4];
        a[0] = *(const unsigned*)&g_z_h[(size_t)(nb + g) * 16 + k0h + t];
        a[1] = *(const unsigned*)&g_z_h[(size_t)(nb + g + 8) * 16 + k0h + t];
        a[2] = *(const unsigned*)&g_z_h[(size_t)(nb + g) * 16 + k0h + t + 4];
        a[3] = *(const unsigned*)&g_z_h[(size_t)(nb + g + 8) * 16 + k0h + t + 4];
        const int k0 = kf * 16;
#pragma unroll
        for (int nf = 0; nf < 8; nf++) {
            unsigned bv[2];
            bv[0] = *(const unsigned*)&sW1h[(nf * 8 + g) * 40 + k0 + 2 * t];
            bv[1] = *(const unsigned*)&sW1h[(nf * 8 + g) * 40 + k0 + 2 * t + 8];
            mma16816(acc[nf], a, bv);
            bv[0] = *(const unsigned*)&sW1l[(nf * 8 + g) * 40 + k0 + 2 * t];
            bv[1] = *(const unsigned*)&sW1l[(nf * 8 + g) * 40 + k0 + 2 * t + 8];
            mma16816(acc[nf], a, bv);
        }
    }

    // ---- bias + relu -> fp16 staging ----
#pragma unroll
    for (int nf = 0; nf < 8; nf++) {
        const int c0 = nf * 8 + 2 * t;
        float h0 = fmaxf(acc[nf][0] + sb1v[c0],     0.f);
        float h1 = fmaxf(acc[nf][1] + sb1v[c0 + 1], 0.f);
        float h2 = fmaxf(acc[nf][2] + sb1v[c0],     0.f);
        float h3 = fmaxf(acc[nf][3] + sb1v[c0 + 1], 0.f);
        *(__half2*)&H[g * 72 + c0]       = __floats2half2_rn(h0, h1);
        *(__half2*)&H[(g + 8) * 72 + c0] = __floats2half2_rn(h2, h3);
    }
    __syncwarp();

    // ---- stage 2: C2[16x64] = h[16x64] @ W2[64x64] ----
    float acc2[8][4];
#pragma unroll
    for (int nf = 0; nf < 8; nf++)
#pragma unroll
        for (int q = 0; q < 4; q++) acc2[nf][q] = 0.f;

#pragma unroll
    for (int kf = 0; kf < 4; kf++) {
        const int k0 = kf * 16;
        unsigned a[4];
        a[0] = *(const unsigned*)&H[g * 72 + k0 + 2 * t];
        a[1] = *(const unsigned*)&H[(g + 8) * 72 + k0 + 2 * t];
        a[2] = *(const unsigned*)&H[g * 72 + k0 + 2 * t + 8];
        a[3] = *(const unsigned*)&H[(g + 8) * 72 + k0 + 2 * t + 8];
#pragma unroll
        for (int nf = 0; nf < 8; nf++) {
            unsigned bv[2];
            bv[0] = *(const unsigned*)&sW2h[(nf * 8 + g) * 72 + k0 + 2 * t];
            bv[1] = *(const unsigned*)&sW2h[(nf * 8 + g) * 72 + k0 + 2 * t + 8];
            mma16816(acc2[nf], a, bv);
            bv[0] = *(const unsigned*)&sW2l[(nf * 8 + g) * 72 + k0 + 2 * t];
            bv[1] = *(const unsigned*)&sW2l[(nf * 8 + g) * 72 + k0 + 2 * t + 8];
            mma16816(acc2[nf], a, bv);
        }
    }

    // ---- dis scale + fp16 write ----
    const float d0 = g_dis[nb + g], d1 = g_dis[nb + g + 8];
    __half2* y0 = g_y_h + (size_t)(nb + g) * 32;
    __half2* y1 = g_y_h + (size_t)(nb + g + 8) * 32;
#pragma unroll
    for (int nf = 0; nf < 8; nf++) {
        const int cw = nf * 4 + t;
        y0[cw] = __floats2half2_rn(acc2[nf][0] * d0, acc2[nf][1] * d0);
        y1[cw] = __floats2half2_rn(acc2[nf][2] * d1, acc2[nf][3] * d1);
    }
}

// ---------------- gather64 + fused mean-pool partial reduction ----------------
__global__ void gather64_pool_kernel(const float* __restrict__ bias) {
    __shared__ float pool[64];
    const __half2* __restrict__ y = g_y_h;
    const int tid = threadIdx.x;
    const int gw = (blockIdx.x * 256 + tid) >> 5;
    const int lane = tid & 31;
    if (tid < 64) pool[tid] = 0.f;
    __syncthreads();

    float2 a = __half22float2(__ldg(&y[gw * 32 + lane]));
    int p = g_off[gw];
    const int e = g_off[gw + 1];
    for (; p + 8 <= e; p += 8) {
        int j0 = __ldg(&g_srcs[p + 0]), j1 = __ldg(&g_srcs[p + 1]);
        int j2 = __ldg(&g_srcs[p + 2]), j3 = __ldg(&g_srcs[p + 3]);
        int j4 = __ldg(&g_srcs[p + 4]), j5 = __ldg(&g_srcs[p + 5]);
        int j6 = __ldg(&g_srcs[p + 6]), j7 = __ldg(&g_srcs[p + 7]);
        float2 v0 = __half22float2(__ldg(&y[j0 * 32 + lane]));
        float2 v1 = __half22float2(__ldg(&y[j1 * 32 + lane]));
        float2 v2 = __half22float2(__ldg(&y[j2 * 32 + lane]));
        float2 v3 = __half22float2(__ldg(&y[j3 * 32 + lane]));
        float2 v4 = __half22float2(__ldg(&y[j4 * 32 + lane]));
        float2 v5 = __half22float2(__ldg(&y[j5 * 32 + lane]));
        float2 v6 = __half22float2(__ldg(&y[j6 * 32 + lane]));
        float2 v7 = __half22float2(__ldg(&y[j7 * 32 + lane]));
        a.x += ((v0.x + v1.x) + (v2.x + v3.x)) + ((v4.x + v5.x) + (v6.x + v7.x));
        a.y += ((v0.y + v1.y) + (v2.y + v3.y)) + ((v4.y + v5.y) + (v6.y + v7.y));
    }
    for (; p < e; p++) {
        int j = __ldg(&g_srcs[p]);
        float2 v = __half22float2(__ldg(&y[j * 32 + lane]));
        a.x += v.x; a.y += v.y;
    }
    const float d = g_dis[gw];
    float2 bb = ((const float2*)bias)[lane];
    float rx = fmaxf(fmaf(d, a.x, bb.x), 0.f);
    float ry = fmaxf(fmaf(d, a.y, bb.y), 0.f);
    atomicAdd(&pool[2 * lane],     rx);
    atomicAdd(&pool[2 * lane + 1], ry);
    __syncthreads();
    if (tid < 64) {
        const int batch = gw >> 11;
        atomicAdd(&g_pool[batch * 64 + tid], pool[tid]);
    }
}

// ---------------- classifier from pooled sums ----------------
__global__ void cls_kernel(const float* __restrict__ clsw,
                           const float* __restrict__ clsb,
                           float* __restrict__ out) {
    __shared__ float sw[64 * OUTC];
    const int tid = threadIdx.x;
    if (tid < 64 * OUTC) sw[tid] = clsw[tid];
    __syncthreads();
    if (tid < BATCH * OUTC) {
        const int b = tid / OUTC, o = tid - b * OUTC;
        float acc = clsb[o];
#pragma unroll
        for (int c = 0; c < 64; c++)
            acc += g_pool[b * 64 + c] * sw[c * OUTC + o];
        out[tid] = acc * (1.f / (float)T4) + clsb[o] * (1.f - 1.f / (float)T4);
    }
}

// ---------------- launch ----------------
extern "C" void kernel_launch(void* const* d_in, const int* in_sizes, int n_in,
                              void* d_out, int out_size) {
    const float* x       = nullptr;
    const int*   ei      = nullptr;
    const float* conv1_w = nullptr; const float* conv1_b = nullptr;
    const float* conv2_w = nullptr; const float* conv2_b = nullptr;
    const float* gcn1_w  = nullptr; const float* gcn1_b  = nullptr;
    const float* gcn2_w  = nullptr; const float* gcn2_b  = nullptr;
    const float* cls_w   = nullptr; const float* cls_b   = nullptr;

    for (int i = 0; i < n_in; i++) {
        switch (in_sizes[i]) {
            case BATCH * 16 * T_IN:   x       = (const float*)d_in[i]; break;
            case 2 * N_EDGES:         ei      = (const int*)  d_in[i]; break;
            case 16 * 16 * 5:         conv1_w = (const float*)d_in[i]; break;
            case 16:                  conv1_b = (const float*)d_in[i]; break;
            case 32 * 16 * 5:         conv2_w = (const float*)d_in[i]; break;
            case 32:                  conv2_b = (const float*)d_in[i]; break;
            case 32 * HID:            gcn1_w  = (const float*)d_in[i]; break;
            case HID * HID:           gcn2_w  = (const float*)d_in[i]; break;
            case HID * OUTC:          cls_w   = (const float*)d_in[i]; break;
            case OUTC:                cls_b   = (const float*)d_in[i]; break;
            case HID:
                if (!gcn1_b) gcn1_b = (const float*)d_in[i];
                else         gcn2_b = (const float*)d_in[i];
                break;
            default: break;
        }
    }
    if (!x || !ei || !conv1_w || !conv2_w || !gcn1_w || !gcn2_w || !cls_w) {
        x       = (const float*)d_in[0];  ei      = (const int*)  d_in[1];
        conv1_w = (const float*)d_in[2];  conv1_b = (const float*)d_in[3];
        conv2_w = (const float*)d_in[4];  conv2_b = (const float*)d_in[5];
        gcn1_w  = (const float*)d_in[6];  gcn1_b  = (const float*)d_in[7];
        gcn2_w  = (const float*)d_in[8];  gcn2_b  = (const float*)d_in[9];
        cls_w   = (const float*)d_in[10]; cls_b   = (const float*)d_in[11];
    }

    float* out = (float*)d_out;
    const int* e_row = ei;
    const int* e_col = ei + N_EDGES;

    cudaFuncSetAttribute(conv_fused_kernel,
                         cudaFuncAttributeMaxDynamicSharedMemorySize, SM_BYTES);

    static cudaStream_t s_side = nullptr;
    static cudaEvent_t  s_fork = nullptr, s_join = nullptr;
    if (!s_side) {
        cudaStreamCreateWithFlags(&s_side, cudaStreamNonBlocking);
        cudaEventCreateWithFlags(&s_fork, cudaEventDisableTiming);
        cudaEventCreateWithFlags(&s_join, cudaEventDisableTiming);
    }

    // serial prefix: counts only (conv derives dis from g_cnt itself)
    zero_cnt_kernel<<<N_NODES / 256, 256>>>();
    hist_kernel<<<N_EDGES / 256, 256>>>(e_col);

    // fork: scans + place (whole CSR tail incl. scan1) overlap conv
    cudaEventRecord(s_fork, 0);
    cudaStreamWaitEvent(s_side, s_fork, 0);
    scan1_kernel<<<128, 256, 0, s_side>>>();       // also computes g_dis
    scan2_kernel<<<1, 128, 0, s_side>>>();
    scan3_kernel<<<N_NODES / 256, 256, 0, s_side>>>();
    place_kernel<<<N_EDGES / 256, 256, 0, s_side>>>(e_row, e_col);
    cudaEventRecord(s_join, s_side);

    {
        dim3 gc(T4 / 128, BATCH);
        conv_fused_kernel<<<gc, 256, SM_BYTES>>>(x, conv1_w, conv1_b, conv2_w, conv2_b);
    }

    cudaStreamWaitEvent(0, s_join, 0);

    gather32_kernel<<<N_NODES / 8, 256>>>();
    xw_mma_kernel<<<N_NODES / 128, 256>>>(gcn1_w, gcn1_b, gcn2_w);
    gather64_pool_kernel<<<N_NODES / 8, 256>>>(gcn2_b);
    cls_kernel<<<1, 640>>>(cls_w, cls_b, out);
}